// round 7
// baseline (speedup 1.0000x reference)
#include <cuda_runtime.h>
#include <cstdint>

#define Bb 8
#define Tt 2048
#define Cc 1024
#define HS 64
#define CH 2              // key-tiles (128 keys) per split-KV chunk
#define NSLOT 8
#define WPB 72            // sum_{rb=0}^{15} ceil((rb+1)/2)

__device__ __align__(16) float g_Q[Bb*Tt*HS];
__device__ __align__(16) float g_K[Bb*Tt*HS];      // stored tf32-rounded
__device__ __align__(16) float g_V[Bb*Tt*HS];      // stored tf32-rounded
__device__ __align__(16) float g_Op[NSLOT*Bb*Tt*HS];
__device__ __align__(16) float g_Lp[NSLOT*Bb*Tt];
__device__ __align__(16) uint32_t g_Wpk[64 * 3200];  // 64 chunks x (16 x 200) tf32 image

__device__ __forceinline__ uint32_t tf32r(float f) {
    uint32_t r; asm("cvt.rna.tf32.f32 %0, %1;" : "=r"(r) : "f"(f)); return r;
}
__device__ __forceinline__ float ex2f(float x) {
    float r; asm("ex2.approx.f32 %0, %1;" : "=f"(r) : "f"(x)); return r;
}
__device__ __forceinline__ void mma8(float4& d, uint32_t a0, uint32_t a1, uint32_t a2, uint32_t a3,
                                     uint32_t b0, uint32_t b1) {
    asm("mma.sync.aligned.m16n8k8.row.col.f32.tf32.tf32.f32 "
        "{%0,%1,%2,%3}, {%4,%5,%6,%7}, {%8,%9}, {%0,%1,%2,%3};"
        : "+f"(d.x), "+f"(d.y), "+f"(d.z), "+f"(d.w)
        : "r"(a0), "r"(a1), "r"(a2), "r"(a3), "r"(b0), "r"(b1));
}
__device__ __forceinline__ uint4 cvt4(float4 v) {
    return make_uint4(tf32r(v.x), tf32r(v.y), tf32r(v.z), tf32r(v.w));
}
__device__ __forceinline__ uint32_t smem_u32(const void* p) {
    uint32_t a;
    asm("{ .reg .u64 t; cvta.to.shared.u64 t, %1; cvt.u32.u64 %0, t; }" : "=r"(a) : "l"(p));
    return a;
}
__device__ __forceinline__ void cpa16(uint32_t dst, const void* src) {
    asm volatile("cp.async.cg.shared.global [%0], [%1], 16;" :: "r"(dst), "l"(src));
}
#define CP_COMMIT() asm volatile("cp.async.commit_group;" ::: "memory")
#define CP_WAIT0()  asm volatile("cp.async.wait_group 0;" ::: "memory")

// ============================================================================
// Prepack weights: tf32-rounded, padded smem-image layout (16 x 200 per chunk).
// ============================================================================
__global__ __launch_bounds__(256) void prep_w(
    const float* __restrict__ Wq, const float* __restrict__ Wk, const float* __restrict__ Wv)
{
    const int ch = blockIdx.x;
    for (int idx = threadIdx.x; idx < 3200; idx += 256) {
        const int r = idx / 200, n = idx % 200;
        uint32_t val = 0u;
        if (n < 192) {
            const float* W = (n < 64) ? Wq : (n < 128) ? Wk : Wv;
            val = tf32r(W[(size_t)(ch * 16 + r) * HS + (n & 63)]);
        }
        g_Wpk[ch * 3200 + idx] = val;
    }
}

// ============================================================================
// Fused QKV: CTA 64x192, BK=16, 8 warps (2m x 4n), warp tile 32x48.
// B via cp.async from prepacked image; A via reg-prefetch + cvt. 1 sync/iter.
// ============================================================================
#define ALD 36
#define BLD 200
__global__ __launch_bounds__(256, 2) void qkv_mma(const float* __restrict__ x)
{
    __shared__ uint32_t As[2][64 * ALD];
    __shared__ uint32_t Bs[2][16 * BLD];
    const int tid = threadIdx.x;
    const int w = tid >> 5, lane = tid & 31;
    const int g = lane >> 2, t = lane & 3;
    const int wm = w >> 2, wn = w & 3;
    const int m0 = blockIdx.x * 64;

    float4 acc[2][6];
    #pragma unroll
    for (int i = 0; i < 2; i++)
        #pragma unroll
        for (int j = 0; j < 6; j++) acc[i][j] = make_float4(0.f, 0.f, 0.f, 0.f);

    const int ar = tid >> 2, ac = (tid & 3) * 4;
    const bool bldr = (tid < 200);
    const uint32_t bs0 = smem_u32(&Bs[0][0]) + (uint32_t)tid * 64;
    const uint32_t bs1 = smem_u32(&Bs[1][0]) + (uint32_t)tid * 64;
    const uint32_t* wsrc = g_Wpk + tid * 16;

    // prologue: B chunk 0 via cp.async, A chunk 0 via regs
    if (bldr) {
        #pragma unroll
        for (int j = 0; j < 4; j++) cpa16(bs0 + j * 16, wsrc + j * 4);
    }
    CP_COMMIT();
    float4 a_s = *(const float4*)(x + (size_t)(m0 + ar) * Cc + ac);

    #pragma unroll 1
    for (int ch = 0; ch < 64; ch++) {
        const int st = ch & 1;
        *(uint4*)(As[st] + ar * ALD + ac) = cvt4(a_s);
        CP_WAIT0();
        __syncthreads();
        if (ch < 63) {
            if (bldr) {
                const uint32_t* src = wsrc + (ch + 1) * 3200;
                const uint32_t dst = (st ? bs0 : bs1);
                #pragma unroll
                for (int j = 0; j < 4; j++) cpa16(dst + j * 16, src + j * 4);
            }
            CP_COMMIT();
            a_s = *(const float4*)(x + (size_t)(m0 + ar) * Cc + (ch + 1) * 16 + ac);
        }
        #pragma unroll
        for (int kk = 0; kk < 2; kk++) {
            uint32_t a[2][4];
            #pragma unroll
            for (int sub = 0; sub < 2; sub++) {
                const int rbase = (wm * 32 + sub * 16 + g) * ALD + kk * 8;
                a[sub][0] = As[st][rbase + t];
                a[sub][1] = As[st][rbase + 8 * ALD + t];
                a[sub][2] = As[st][rbase + t + 4];
                a[sub][3] = As[st][rbase + 8 * ALD + t + 4];
            }
            #pragma unroll
            for (int ns = 0; ns < 6; ns++) {
                uint32_t b0 = Bs[st][(kk * 8 + t) * BLD + wn * 48 + ns * 8 + g];
                uint32_t b1 = Bs[st][(kk * 8 + t + 4) * BLD + wn * 48 + ns * 8 + g];
                #pragma unroll
                for (int sub = 0; sub < 2; sub++)
                    mma8(acc[sub][ns], a[sub][0], a[sub][1], a[sub][2], a[sub][3], b0, b1);
            }
        }
    }
    // epilogue: Q raw; K,V rounded to tf32 (so attn can stage without cvt)
    #pragma unroll
    for (int sub = 0; sub < 2; sub++) {
        #pragma unroll
        for (int ns = 0; ns < 6; ns++) {
            const int cb = wn * 48 + ns * 8;
            float* base = (cb < 64) ? g_Q : (cb < 128) ? g_K : g_V;
            const bool rnd = (cb >= 64);
            const int c = (cb & 63) + 2 * t;
            const size_t r = (size_t)(m0 + wm * 32 + sub * 16 + g);
            float4 v = acc[sub][ns];
            if (rnd) {
                v.x = __uint_as_float(tf32r(v.x)); v.y = __uint_as_float(tf32r(v.y));
                v.z = __uint_as_float(tf32r(v.z)); v.w = __uint_as_float(tf32r(v.w));
            }
            *(float2*)(base + r * HS + c)       = make_float2(v.x, v.y);
            *(float2*)(base + (r + 8) * HS + c) = make_float2(v.z, v.w);
        }
    }
}

// ============================================================================
// Split-KV causal attention. Fused per-8-key-subtile S -> softmax -> PV keeps
// live registers ~100 -> 2 CTAs/SM. K/V staged raw via cp.async (pre-rounded).
// ============================================================================
#define KLDK 68
#define KLDV 72
#define SMEM_ATTN ((128 * KLDK + 128 * KLDV) * 4)

__global__ __launch_bounds__(256, 2) void attn_part(void)
{
    extern __shared__ uint32_t sm[];
    uint32_t* Ks = sm;
    uint32_t* Vs = sm + 128 * KLDK;
    const uint32_t ks_b = smem_u32(Ks), vs_b = smem_u32(Vs);

    // decode work item (heavy chunks first)
    const int item = (gridDim.x - 1) - blockIdx.x;
    const int b = item / WPB;
    int r = item % WPB, rb = 0;
    #pragma unroll 1
    while (true) { int n = (rb + 2) >> 1; if (r < n) break; r -= n; rb++; }
    const int chunk = r;
    const int t0 = chunk * CH;
    const int t1 = (t0 + CH < rb + 1) ? (t0 + CH) : (rb + 1);
    const int qbase = rb * 128;

    const int tid = threadIdx.x;
    const int w = tid >> 5, lane = tid & 31;
    const int g = lane >> 2, t = lane & 3;
    const int qrow_lo = qbase + w * 16 + g;
    const int qrow_hi = qrow_lo + 8;

    // Q fragments in registers (scaled by log2e/32, tf32)
    const float qscale = 1.4426950408889634f / 32.0f;
    uint32_t aq[8][4];
    {
        const float* r0 = g_Q + ((size_t)b * Tt + qrow_lo) * HS;
        const float* r1 = r0 + 8 * HS;
        #pragma unroll
        for (int kk = 0; kk < 8; kk++) {
            aq[kk][0] = tf32r(r0[kk * 8 + t] * qscale);
            aq[kk][1] = tf32r(r1[kk * 8 + t] * qscale);
            aq[kk][2] = tf32r(r0[kk * 8 + t + 4] * qscale);
            aq[kk][3] = tf32r(r1[kk * 8 + t + 4] * qscale);
        }
    }

    float4 acc_o[8];
    #pragma unroll
    for (int i = 0; i < 8; i++) acc_o[i] = make_float4(0.f, 0.f, 0.f, 0.f);
    float lsum_lo = 0.f, lsum_hi = 0.f;

    const float* Kg = g_K + (size_t)b * Tt * HS;
    const float* Vg = g_V + (size_t)b * Tt * HS;
    const int srcq0 = (lane & ~3) | (t >> 1);
    const int srcq1 = srcq0 | 2;
    const bool odd = (t & 1);
    const int crr = (tid + 0) >> 4;           // staging row for this thread (i folded below)
    (void)crr;

    #pragma unroll 1
    for (int tt = t0; tt < t1; tt++) {
        const int j0 = tt * 128;
        __syncthreads();   // previous tile fully consumed
        #pragma unroll
        for (int i = 0; i < 8; i++) {
            int u = tid + i * 256;
            int rr = u >> 4, c = (u & 15) * 4;
            cpa16(ks_b + (uint32_t)(rr * KLDK + c) * 4, Kg + (size_t)(j0 + rr) * HS + c);
            cpa16(vs_b + (uint32_t)(rr * KLDV + c) * 4, Vg + (size_t)(j0 + rr) * HS + c);
        }
        CP_COMMIT();
        CP_WAIT0();
        __syncthreads();

        const bool last_tile = (tt == rb);
        #pragma unroll 1
        for (int ns = 0; ns < 16; ns++) {
            // ---- S subtile (128 q-rows x 8 keys per warp slice) ----
            float4 cs = make_float4(0.f, 0.f, 0.f, 0.f);
            #pragma unroll
            for (int kk = 0; kk < 8; kk++) {
                uint32_t b0 = Ks[(ns * 8 + g) * KLDK + kk * 8 + t];
                uint32_t b1 = Ks[(ns * 8 + g) * KLDK + kk * 8 + t + 4];
                mma8(cs, aq[kk][0], aq[kk][1], aq[kk][2], aq[kk][3], b0, b1);
            }
            // ---- softmax + mask + tf32 round ----
            float px = ex2f(cs.x), py = ex2f(cs.y), pz = ex2f(cs.z), pw = ex2f(cs.w);
            if (last_tile) {
                const int cx = j0 + ns * 8 + 2 * t, cy = cx + 1;
                if (cx > qrow_lo) px = 0.f;
                if (cy > qrow_lo) py = 0.f;
                if (cx > qrow_hi) pz = 0.f;
                if (cy > qrow_hi) pw = 0.f;
            }
            uint32_t ux = tf32r(px), uy = tf32r(py), uz = tf32r(pz), uw = tf32r(pw);
            lsum_lo += __uint_as_float(ux) + __uint_as_float(uy);
            lsum_hi += __uint_as_float(uz) + __uint_as_float(uw);
            // ---- C-frag -> A-frag (intra-quad shuffles) ----
            uint32_t xA = __shfl_sync(0xffffffffu, ux, srcq0);
            uint32_t yA = __shfl_sync(0xffffffffu, uy, srcq0);
            uint32_t zA = __shfl_sync(0xffffffffu, uz, srcq0);
            uint32_t wA = __shfl_sync(0xffffffffu, uw, srcq0);
            uint32_t xB = __shfl_sync(0xffffffffu, ux, srcq1);
            uint32_t yB = __shfl_sync(0xffffffffu, uy, srcq1);
            uint32_t zB = __shfl_sync(0xffffffffu, uz, srcq1);
            uint32_t wB = __shfl_sync(0xffffffffu, uw, srcq1);
            uint32_t a0 = odd ? yA : xA;
            uint32_t a1 = odd ? wA : zA;
            uint32_t a2 = odd ? yB : xB;
            uint32_t a3 = odd ? wB : zB;
            // ---- PV: O += P[:, ns*8..+8] * V[ns*8..+8, :] ----
            #pragma unroll
            for (int ns2 = 0; ns2 < 8; ns2++) {
                uint32_t b0 = Vs[(ns * 8 + t) * KLDV + ns2 * 8 + g];
                uint32_t b1 = Vs[(ns * 8 + t + 4) * KLDV + ns2 * 8 + g];
                mma8(acc_o[ns2], a0, a1, a2, a3, b0, b1);
            }
        }
    }

    // ---- write partial O (unnormalized) and partial l ----
    float llo = lsum_lo;
    llo += __shfl_xor_sync(0xffffffffu, llo, 1);
    llo += __shfl_xor_sync(0xffffffffu, llo, 2);
    float lhi = lsum_hi;
    lhi += __shfl_xor_sync(0xffffffffu, lhi, 1);
    lhi += __shfl_xor_sync(0xffffffffu, lhi, 2);

    float* baseo = g_Op + (((size_t)chunk * Bb + b) * Tt + qrow_lo) * HS;
    #pragma unroll
    for (int ns2 = 0; ns2 < 8; ns2++) {
        *(float2*)(baseo + ns2 * 8 + 2 * t)          = make_float2(acc_o[ns2].x, acc_o[ns2].y);
        *(float2*)(baseo + 8 * HS + ns2 * 8 + 2 * t) = make_float2(acc_o[ns2].z, acc_o[ns2].w);
    }
    if (t == 0) {
        g_Lp[((size_t)chunk * Bb + b) * Tt + qrow_lo] = llo;
        g_Lp[((size_t)chunk * Bb + b) * Tt + qrow_hi] = lhi;
    }
}

// ============================================================================
// Combine: out = (sum_s O_s) / (sum_s l_s) over exactly nch(rb) slots.
// ============================================================================
__global__ __launch_bounds__(256) void attn_combine(float* __restrict__ out)
{
    const int idx = blockIdx.x * 256 + threadIdx.x;
    const int row = idx >> 6;
    const int d   = idx & 63;
    const int trow = row & (Tt - 1);
    const int b    = row >> 11;
    const int rb   = trow >> 7;
    const int nch  = (rb + 2) >> 1;

    float o = 0.f, l = 0.f;
    #pragma unroll 1
    for (int s = 0; s < nch; s++) {
        o += g_Op[(((size_t)s * Bb + b) * Tt + trow) * HS + d];
        l += g_Lp[((size_t)s * Bb + b) * Tt + trow];
    }
    out[idx] = o / l;
}

// ============================================================================
extern "C" void kernel_launch(void* const* d_in, const int* in_sizes, int n_in,
                              void* d_out, int out_size)
{
    const float* x  = (const float*)d_in[0];
    const float* Wq = (const float*)d_in[1];
    const float* Wk = (const float*)d_in[2];
    const float* Wv = (const float*)d_in[3];
    float* out = (float*)d_out;

    prep_w<<<64, 256>>>(Wq, Wk, Wv);
    qkv_mma<<<(Bb * Tt) / 64, 256>>>(x);

    cudaFuncSetAttribute(attn_part, cudaFuncAttributeMaxDynamicSharedMemorySize, SMEM_ATTN);
    attn_part<<<Bb * WPB, 256, SMEM_ATTN>>>();

    attn_combine<<<(Bb * Tt * HS) / 256, 256>>>(out);
}

// round 8
// speedup vs baseline: 1.1227x; 1.1227x over previous
#include <cuda_runtime.h>
#include <cstdint>

#define Bb 8
#define Tt 2048
#define Cc 1024
#define HS 64
#define CH 4              // key-tiles (128 keys) per split-KV chunk
#define NSLOT 4
#define WPB 40            // sum_{rb=0}^{15} ceil((rb+1)/4)

__device__ __align__(16) float g_Q[Bb*Tt*HS];
__device__ __align__(16) float g_K[Bb*Tt*HS];      // stored tf32-rounded
__device__ __align__(16) float g_V[Bb*Tt*HS];      // stored tf32-rounded
__device__ __align__(16) float g_Op[NSLOT*Bb*Tt*HS];
__device__ __align__(16) float g_Lp[NSLOT*Bb*Tt];

__device__ __forceinline__ uint32_t tf32r(float f) {
    uint32_t r; asm("cvt.rna.tf32.f32 %0, %1;" : "=r"(r) : "f"(f)); return r;
}
__device__ __forceinline__ float ex2f(float x) {
    float r; asm("ex2.approx.f32 %0, %1;" : "=f"(r) : "f"(x)); return r;
}
__device__ __forceinline__ void mma8(float4& d, uint32_t a0, uint32_t a1, uint32_t a2, uint32_t a3,
                                     uint32_t b0, uint32_t b1) {
    asm("mma.sync.aligned.m16n8k8.row.col.f32.tf32.tf32.f32 "
        "{%0,%1,%2,%3}, {%4,%5,%6,%7}, {%8,%9}, {%0,%1,%2,%3};"
        : "+f"(d.x), "+f"(d.y), "+f"(d.z), "+f"(d.w)
        : "r"(a0), "r"(a1), "r"(a2), "r"(a3), "r"(b0), "r"(b1));
}
__device__ __forceinline__ uint4 cvt4(float4 v) {
    return make_uint4(tf32r(v.x), tf32r(v.y), tf32r(v.z), tf32r(v.w));
}
__device__ __forceinline__ uint32_t smem_u32(const void* p) {
    uint32_t a;
    asm("{ .reg .u64 t; cvta.to.shared.u64 t, %1; cvt.u32.u64 %0, t; }" : "=r"(a) : "l"(p));
    return a;
}
__device__ __forceinline__ void cpa16(uint32_t dst, const void* src) {
    asm volatile("cp.async.cg.shared.global [%0], [%1], 16;" :: "r"(dst), "l"(src));
}
#define CP_COMMIT() asm volatile("cp.async.commit_group;" ::: "memory")
#define CP_WAIT0()  asm volatile("cp.async.wait_group 0;" ::: "memory")

// ============================================================================
// Fused QKV (R6 body, measured 69.7us): CTA 64x192, BK=16, 8 warps (2m x 4n),
// warp tile 32x48, ping-pong smem, 1 sync/iter, 2 CTAs/SM.
// Epilogue stores K/V tf32-rounded so attn can cp.async-stage without cvt.
// ============================================================================
#define ALD 36
#define BLD 200
__global__ __launch_bounds__(256, 2) void qkv_mma(
    const float* __restrict__ x, const float* __restrict__ Wq,
    const float* __restrict__ Wk, const float* __restrict__ Wv)
{
    __shared__ uint32_t As[2][64 * ALD];
    __shared__ uint32_t Bs[2][16 * BLD];
    const int tid = threadIdx.x;
    const int w = tid >> 5, lane = tid & 31;
    const int g = lane >> 2, t = lane & 3;
    const int wm = w >> 2, wn = w & 3;
    const int m0 = blockIdx.x * 64;

    float4 acc[2][6];
    #pragma unroll
    for (int i = 0; i < 2; i++)
        #pragma unroll
        for (int j = 0; j < 6; j++) acc[i][j] = make_float4(0.f, 0.f, 0.f, 0.f);

    const int ar = tid >> 2, ac = (tid & 3) * 4;
    const int wkr = tid >> 4, wcc = (tid & 15) * 4;

    float4 a_s = *(const float4*)(x + (size_t)(m0 + ar) * Cc + ac);
    float4 q_s = *(const float4*)(Wq + (size_t)wkr * HS + wcc);
    float4 k_s = *(const float4*)(Wk + (size_t)wkr * HS + wcc);
    float4 v_s = *(const float4*)(Wv + (size_t)wkr * HS + wcc);

    #pragma unroll 1
    for (int ch = 0; ch < 64; ch++) {
        const int st = ch & 1;
        *(uint4*)(As[st] + ar * ALD + ac)         = cvt4(a_s);
        *(uint4*)(Bs[st] + wkr * BLD + wcc)       = cvt4(q_s);
        *(uint4*)(Bs[st] + wkr * BLD + 64 + wcc)  = cvt4(k_s);
        *(uint4*)(Bs[st] + wkr * BLD + 128 + wcc) = cvt4(v_s);
        __syncthreads();
        if (ch < 63) {
            const int k0 = (ch + 1) * 16;
            a_s = *(const float4*)(x + (size_t)(m0 + ar) * Cc + k0 + ac);
            q_s = *(const float4*)(Wq + (size_t)(k0 + wkr) * HS + wcc);
            k_s = *(const float4*)(Wk + (size_t)(k0 + wkr) * HS + wcc);
            v_s = *(const float4*)(Wv + (size_t)(k0 + wkr) * HS + wcc);
        }
        #pragma unroll
        for (int kk = 0; kk < 2; kk++) {
            uint32_t a[2][4];
            #pragma unroll
            for (int sub = 0; sub < 2; sub++) {
                const int rbase = (wm * 32 + sub * 16 + g) * ALD + kk * 8;
                a[sub][0] = As[st][rbase + t];
                a[sub][1] = As[st][rbase + 8 * ALD + t];
                a[sub][2] = As[st][rbase + t + 4];
                a[sub][3] = As[st][rbase + 8 * ALD + t + 4];
            }
            #pragma unroll
            for (int ns = 0; ns < 6; ns++) {
                uint32_t b0 = Bs[st][(kk * 8 + t) * BLD + wn * 48 + ns * 8 + g];
                uint32_t b1 = Bs[st][(kk * 8 + t + 4) * BLD + wn * 48 + ns * 8 + g];
                #pragma unroll
                for (int sub = 0; sub < 2; sub++)
                    mma8(acc[sub][ns], a[sub][0], a[sub][1], a[sub][2], a[sub][3], b0, b1);
            }
        }
    }
    #pragma unroll
    for (int sub = 0; sub < 2; sub++) {
        #pragma unroll
        for (int ns = 0; ns < 6; ns++) {
            const int cb = wn * 48 + ns * 8;
            float* base = (cb < 64) ? g_Q : (cb < 128) ? g_K : g_V;
            const bool rnd = (cb >= 64);
            const int c = (cb & 63) + 2 * t;
            const size_t r = (size_t)(m0 + wm * 32 + sub * 16 + g);
            float4 v = acc[sub][ns];
            if (rnd) {
                v.x = __uint_as_float(tf32r(v.x)); v.y = __uint_as_float(tf32r(v.y));
                v.z = __uint_as_float(tf32r(v.z)); v.w = __uint_as_float(tf32r(v.w));
            }
            *(float2*)(base + r * HS + c)       = make_float2(v.x, v.y);
            *(float2*)(base + (r + 8) * HS + c) = make_float2(v.z, v.w);
        }
    }
}

// ============================================================================
// Split-KV causal attention, fused per-8-key S -> softmax -> PV, 2 CTAs/SM.
// K/V staged raw via cp.async (pre-rounded tf32 from qkv epilogue).
// ============================================================================
#define KLDK 68
#define KLDV 72
#define SMEM_ATTN ((128 * KLDK + 128 * KLDV) * 4)

__global__ __launch_bounds__(256, 2) void attn_part(void)
{
    extern __shared__ uint32_t sm[];
    uint32_t* Ks = sm;
    uint32_t* Vs = sm + 128 * KLDK;
    const uint32_t ks_b = smem_u32(Ks), vs_b = smem_u32(Vs);

    // decode work item (heavy chunks first)
    const int item = (gridDim.x - 1) - blockIdx.x;
    const int b = item / WPB;
    int r = item % WPB, rb = 0;
    #pragma unroll 1
    while (true) { int n = (rb + CH) >> 2; if (r < n) break; r -= n; rb++; }
    const int chunk = r;
    const int t0 = chunk * CH;
    const int t1 = (t0 + CH < rb + 1) ? (t0 + CH) : (rb + 1);
    const int qbase = rb * 128;

    const int tid = threadIdx.x;
    const int w = tid >> 5, lane = tid & 31;
    const int g = lane >> 2, t = lane & 3;
    const int qrow_lo = qbase + w * 16 + g;
    const int qrow_hi = qrow_lo + 8;

    // Q fragments in registers (scaled by log2e/32, tf32)
    const float qscale = 1.4426950408889634f / 32.0f;
    uint32_t aq[8][4];
    {
        const float* r0 = g_Q + ((size_t)b * Tt + qrow_lo) * HS;
        const float* r1 = r0 + 8 * HS;
        #pragma unroll
        for (int kk = 0; kk < 8; kk++) {
            aq[kk][0] = tf32r(r0[kk * 8 + t] * qscale);
            aq[kk][1] = tf32r(r1[kk * 8 + t] * qscale);
            aq[kk][2] = tf32r(r0[kk * 8 + t + 4] * qscale);
            aq[kk][3] = tf32r(r1[kk * 8 + t + 4] * qscale);
        }
    }

    float4 acc_o[8];
    #pragma unroll
    for (int i = 0; i < 8; i++) acc_o[i] = make_float4(0.f, 0.f, 0.f, 0.f);
    float lsum_lo = 0.f, lsum_hi = 0.f;

    const float* Kg = g_K + (size_t)b * Tt * HS;
    const float* Vg = g_V + (size_t)b * Tt * HS;
    const int srcq0 = (lane & ~3) | (t >> 1);
    const int srcq1 = srcq0 | 2;
    const bool odd = (t & 1);

    #pragma unroll 1
    for (int tt = t0; tt < t1; tt++) {
        const int j0 = tt * 128;
        __syncthreads();
        #pragma unroll
        for (int i = 0; i < 8; i++) {
            int u = tid + i * 256;
            int rr = u >> 4, c = (u & 15) * 4;
            cpa16(ks_b + (uint32_t)(rr * KLDK + c) * 4, Kg + (size_t)(j0 + rr) * HS + c);
            cpa16(vs_b + (uint32_t)(rr * KLDV + c) * 4, Vg + (size_t)(j0 + rr) * HS + c);
        }
        CP_COMMIT();
        CP_WAIT0();
        __syncthreads();

        const bool last_tile = (tt == rb);
        #pragma unroll 1
        for (int ns = 0; ns < 16; ns++) {
            float4 cs = make_float4(0.f, 0.f, 0.f, 0.f);
            #pragma unroll
            for (int kk = 0; kk < 8; kk++) {
                uint32_t b0 = Ks[(ns * 8 + g) * KLDK + kk * 8 + t];
                uint32_t b1 = Ks[(ns * 8 + g) * KLDK + kk * 8 + t + 4];
                mma8(cs, aq[kk][0], aq[kk][1], aq[kk][2], aq[kk][3], b0, b1);
            }
            float px = ex2f(cs.x), py = ex2f(cs.y), pz = ex2f(cs.z), pw = ex2f(cs.w);
            if (last_tile) {
                const int cx = j0 + ns * 8 + 2 * t, cy = cx + 1;
                if (cx > qrow_lo) px = 0.f;
                if (cy > qrow_lo) py = 0.f;
                if (cx > qrow_hi) pz = 0.f;
                if (cy > qrow_hi) pw = 0.f;
            }
            uint32_t ux = tf32r(px), uy = tf32r(py), uz = tf32r(pz), uw = tf32r(pw);
            lsum_lo += __uint_as_float(ux) + __uint_as_float(uy);
            lsum_hi += __uint_as_float(uz) + __uint_as_float(uw);
            uint32_t xA = __shfl_sync(0xffffffffu, ux, srcq0);
            uint32_t yA = __shfl_sync(0xffffffffu, uy, srcq0);
            uint32_t zA = __shfl_sync(0xffffffffu, uz, srcq0);
            uint32_t wA = __shfl_sync(0xffffffffu, uw, srcq0);
            uint32_t xB = __shfl_sync(0xffffffffu, ux, srcq1);
            uint32_t yB = __shfl_sync(0xffffffffu, uy, srcq1);
            uint32_t zB = __shfl_sync(0xffffffffu, uz, srcq1);
            uint32_t wB = __shfl_sync(0xffffffffu, uw, srcq1);
            uint32_t a0 = odd ? yA : xA;
            uint32_t a1 = odd ? wA : zA;
            uint32_t a2 = odd ? yB : xB;
            uint32_t a3 = odd ? wB : zB;
            #pragma unroll
            for (int ns2 = 0; ns2 < 8; ns2++) {
                uint32_t b0 = Vs[(ns * 8 + t) * KLDV + ns2 * 8 + g];
                uint32_t b1 = Vs[(ns * 8 + t + 4) * KLDV + ns2 * 8 + g];
                mma8(acc_o[ns2], a0, a1, a2, a3, b0, b1);
            }
        }
    }

    float llo = lsum_lo;
    llo += __shfl_xor_sync(0xffffffffu, llo, 1);
    llo += __shfl_xor_sync(0xffffffffu, llo, 2);
    float lhi = lsum_hi;
    lhi += __shfl_xor_sync(0xffffffffu, lhi, 1);
    lhi += __shfl_xor_sync(0xffffffffu, lhi, 2);

    float* baseo = g_Op + (((size_t)chunk * Bb + b) * Tt + qrow_lo) * HS;
    #pragma unroll
    for (int ns2 = 0; ns2 < 8; ns2++) {
        *(float2*)(baseo + ns2 * 8 + 2 * t)          = make_float2(acc_o[ns2].x, acc_o[ns2].y);
        *(float2*)(baseo + 8 * HS + ns2 * 8 + 2 * t) = make_float2(acc_o[ns2].z, acc_o[ns2].w);
    }
    if (t == 0) {
        g_Lp[((size_t)chunk * Bb + b) * Tt + qrow_lo] = llo;
        g_Lp[((size_t)chunk * Bb + b) * Tt + qrow_hi] = lhi;
    }
}

// ============================================================================
// Combine: out = (sum_s O_s) / (sum_s l_s), float4 per thread, <=4 slots.
// ============================================================================
__global__ __launch_bounds__(256) void attn_combine(float* __restrict__ out)
{
    const int idx4 = blockIdx.x * 256 + threadIdx.x;   // over B*T*(HS/4)
    const int row  = idx4 >> 4;
    const int d4   = (idx4 & 15) * 4;
    const int trow = row & (Tt - 1);
    const int b    = row >> 11;
    const int rb   = trow >> 7;
    const int nch  = (rb + CH) >> 2;    // ceil((rb+1)/CH)

    float4 o = make_float4(0.f, 0.f, 0.f, 0.f);
    float l = 0.f;
    #pragma unroll
    for (int s = 0; s < NSLOT; s++) {
        if (s < nch) {
            float4 v = *(const float4*)(g_Op + (((size_t)s * Bb + b) * Tt + trow) * HS + d4);
            o.x += v.x; o.y += v.y; o.z += v.z; o.w += v.w;
            l += g_Lp[((size_t)s * Bb + b) * Tt + trow];
        }
    }
    const float rl = 1.0f / l;
    float4 res = make_float4(o.x * rl, o.y * rl, o.z * rl, o.w * rl);
    *(float4*)(out + (size_t)row * HS + d4) = res;
}

// ============================================================================
extern "C" void kernel_launch(void* const* d_in, const int* in_sizes, int n_in,
                              void* d_out, int out_size)
{
    const float* x  = (const float*)d_in[0];
    const float* Wq = (const float*)d_in[1];
    const float* Wk = (const float*)d_in[2];
    const float* Wv = (const float*)d_in[3];
    float* out = (float*)d_out;

    qkv_mma<<<(Bb * Tt) / 64, 256>>>(x, Wq, Wk, Wv);

    cudaFuncSetAttribute(attn_part, cudaFuncAttributeMaxDynamicSharedMemorySize, SMEM_ATTN);
    attn_part<<<Bb * WPB, 256, SMEM_ATTN>>>();

    attn_combine<<<(Bb * Tt * (HS / 4)) / 256, 256>>>(out);
}